// round 6
// baseline (speedup 1.0000x reference)
#include <cuda_runtime.h>
#include <cstdint>

// GraphAttention: B=32768, N=16, FIN=64, H=4, FO=32 (C = H*FO = 128)
// One warp per batch, 2 CTAs/SM (16 warps = full 64K-reg RF at 128 regs).
// fp32 packed f32x2 FMA GEMM nf = x @ W. Scores fold to s = x @ wfold
// (reference einsum sums nf over heads). 4-neighbor softmax {i-1,i,i+1,i^8}.
// R6: cross-batch LDG prefetch (issued after last xd read, consumed next
// iter) + syncwarp diet (5 -> 3).

typedef unsigned long long ull;
struct alignas(16) ull2 { ull a, b; };

static __device__ __forceinline__ void ffma2(ull& d, ull a, ull b) {
    asm("fma.rn.f32x2 %0, %1, %2, %0;" : "+l"(d) : "l"(a), "l"(b));
}
static __device__ __forceinline__ ull pack2(float lo, float hi) {
    ull r; asm("mov.b64 %0, {%1, %2};" : "=l"(r) : "f"(lo), "f"(hi)); return r;
}

constexpr int WARPS   = 8;
constexpr int THREADS = WARPS * 32;
constexpr int XST2    = 66;    // float2 stride of duplicated-x rows

__host__ __device__ constexpr unsigned kMaskFn(int i) {
    unsigned m = (1u << i) | (1u << (i ^ 8));
    if (i > 0)  m |= 1u << (i - 1);
    if (i < 15) m |= 1u << (i + 1);
    return m;
}

__device__ float g_av[256];   // selected att_vec

__global__ void select_av_kernel(const float* __restrict__ cand_a,
                                 const float* __restrict__ cand_b)
{
    __shared__ int a_nonbin;
    int t = threadIdx.x;             // 256 threads
    if (t == 0) a_nonbin = 0;
    __syncthreads();
    float va = cand_a[t];
    if (!(va == 0.0f || va == 1.0f)) atomicAdd(&a_nonbin, 1);
    __syncthreads();
    const float* src = (a_nonbin > 0) ? cand_a : cand_b;
    g_av[t] = src[t];
}

struct SmemLayout {
    float  Ws[64][128];               // W row-major                     32 KB
    float  wfold[64][2][4];           // folded score weights             2 KB
    float2 xdup[WARPS][16 * XST2];    // duplicated x {v,v}            ~66 KB
    float  sbuf[WARPS][2][16][4];     // s1/s2 per node per head          4 KB
    float  ash[WARPS][16][4][4];      // attn[i][slot][h]                 8 KB
};                                    // total ~112 KB -> 2 CTAs/SM

__global__ void __launch_bounds__(THREADS, 2)
gat_kernel(const float* __restrict__ x, const float* __restrict__ W,
           float* __restrict__ out, int n_batch, int total_warps)
{
    extern __shared__ char sraw[];
    SmemLayout* sm = reinterpret_cast<SmemLayout*>(sraw);
    const int tid  = threadIdx.x;
    const int lane = tid & 31;
    const int wid  = tid >> 5;

    // ---- CTA init: copy W; build wfold from W and g_av.
    {
        const float4* Wg = reinterpret_cast<const float4*>(W);
        float4* Wd = reinterpret_cast<float4*>(&sm->Ws[0][0]);
        for (int idx = tid; idx < 64 * 32; idx += THREADS) Wd[idx] = Wg[idx];
        for (int e = tid; e < 512; e += THREADS) {
            int f = e >> 3, side = (e >> 2) & 1, h = e & 3;
            const float* wr = W + f * 128;
            const float* ar = g_av + h * 64 + side * 32;
            float s = 0.f;
            #pragma unroll 8
            for (int f2 = 0; f2 < 32; f2++) {
                float wsum = wr[f2] + wr[32 + f2] + wr[64 + f2] + wr[96 + f2];
                s += wsum * ar[f2];
            }
            sm->wfold[f][side][h] = s;
        }
    }
    __syncthreads();

    float2* xd = sm->xdup[wid];
    const int gw  = blockIdx.x * WARPS + wid;
    const int myh = lane >> 3;   // head owned by this lane's 4 columns

    // ---- prologue: prefetch first batch
    float4 v[8];
    if (gw < n_batch) {
        const float4* xg = reinterpret_cast<const float4*>(x + (size_t)gw * 1024);
        #pragma unroll
        for (int t = 0; t < 8; t++) v[t] = xg[t * 32 + lane];
    }

    for (int b = gw; b < n_batch; b += total_warps) {
        // ---- dup-store prefetched x_b into shared {v,v} layout
        #pragma unroll
        for (int t = 0; t < 8; t++) {
            int g4 = t * 32 + lane;
            int i = g4 >> 4, f0 = (g4 & 15) * 4;
            float2* d = &xd[i * XST2 + f0];
            d[0] = make_float2(v[t].x, v[t].x);
            d[1] = make_float2(v[t].y, v[t].y);
            d[2] = make_float2(v[t].z, v[t].z);
            d[3] = make_float2(v[t].w, v[t].w);
        }
        __syncwarp();

        // ---- GEMM: acc[i][0] = nf cols {4l,4l+1}, acc[i][1] = {4l+2,4l+3}
        ull acc[16][2];
        #pragma unroll
        for (int i = 0; i < 16; i++) { acc[i][0] = 0ull; acc[i][1] = 0ull; }

        #pragma unroll 2
        for (int f = 0; f < 64; f += 2) {
            ull2 w0 = *reinterpret_cast<const ull2*>(&sm->Ws[f][4 * lane]);
            ull2 w1 = *reinterpret_cast<const ull2*>(&sm->Ws[f + 1][4 * lane]);
            #pragma unroll
            for (int i = 0; i < 16; i++) {
                ull2 xv = *reinterpret_cast<const ull2*>(&xd[i * XST2 + f]);
                ffma2(acc[i][0], xv.a, w0.a);
                ffma2(acc[i][1], xv.a, w0.b);
                ffma2(acc[i][0], xv.b, w1.a);
                ffma2(acc[i][1], xv.b, w1.b);
            }
        }

        // ---- s-phase (last reader of xd): s[side][si][h] = x[si,:].wfold[:,side,h]
        {
            int si = lane & 15, side = lane >> 4;
            const float4* xq = reinterpret_cast<const float4*>(&xd[si * XST2]);
            float s0 = 0.f, s1 = 0.f, s2 = 0.f, s3 = 0.f;
            #pragma unroll 8
            for (int k = 0; k < 32; k++) {
                float4 q  = xq[k];   // {x_{2k}, x_{2k}, x_{2k+1}, x_{2k+1}}
                float4 wA = *reinterpret_cast<const float4*>(&sm->wfold[2 * k][side][0]);
                float4 wB = *reinterpret_cast<const float4*>(&sm->wfold[2 * k + 1][side][0]);
                s0 += q.x * wA.x + q.z * wB.x;
                s1 += q.x * wA.y + q.z * wB.y;
                s2 += q.x * wA.z + q.z * wB.z;
                s3 += q.x * wA.w + q.z * wB.w;
            }
            *reinterpret_cast<float4*>(&sm->sbuf[wid][side][si][0]) =
                make_float4(s0, s1, s2, s3);
        }
        __syncwarp();   // sbuf visible; also orders xd reads before next store

        // ---- prefetch next batch's x (latency hides behind softmax+agg+GEMM)
        {
            int bn = b + total_warps;
            if (bn < n_batch) {
                const float4* xg = reinterpret_cast<const float4*>(x + (size_t)bn * 1024);
                #pragma unroll
                for (int t = 0; t < 8; t++) v[t] = xg[t * 32 + lane];
            }
        }

        // ---- softmax over {i-1, i, i+1, i^8}: lane -> (node i, head pair hp)
        {
            int i = lane & 15, hp = lane >> 4;
            float2 s1v = *reinterpret_cast<const float2*>(&sm->sbuf[wid][0][i][2 * hp]);
            int  jn[4] = { (i > 0) ? i - 1 : i, i, (i < 15) ? i + 1 : i, i ^ 8 };
            bool vl[4] = { i > 0, true, i < 15, true };
            float t0[4], t1[4];
            float m0 = -1e30f, m1 = -1e30f;
            #pragma unroll
            for (int s = 0; s < 4; s++) {
                float2 s2v = *reinterpret_cast<const float2*>(&sm->sbuf[wid][1][jn[s]][2 * hp]);
                float a0 = s1v.x + s2v.x; a0 = fmaxf(a0, 0.2f * a0);
                float a1 = s1v.y + s2v.y; a1 = fmaxf(a1, 0.2f * a1);
                t0[s] = vl[s] ? a0 : -1e30f;
                t1[s] = vl[s] ? a1 : -1e30f;
                m0 = fmaxf(m0, t0[s]); m1 = fmaxf(m1, t1[s]);
            }
            float sum0 = 0.f, sum1 = 0.f;
            #pragma unroll
            for (int s = 0; s < 4; s++) {
                t0[s] = __expf(t0[s] - m0);   // invalid -> 0
                t1[s] = __expf(t1[s] - m1);
                sum0 += t0[s]; sum1 += t1[s];
            }
            float r0 = __fdividef(1.f, sum0), r1 = __fdividef(1.f, sum1);
            #pragma unroll
            for (int s = 0; s < 4; s++)
                *reinterpret_cast<float2*>(&sm->ash[wid][i][s][2 * hp]) =
                    make_float2(t0[s] * r0, t1[s] * r1);
        }
        __syncwarp();

        // ---- agg over compile-time masked (i,j) + STG.128 store
        float* ob = out + (size_t)b * 2048;
        #pragma unroll
        for (int i = 0; i < 16; i++) {
            ull o0 = 0ull, o1 = 0ull;
            #pragma unroll
            for (int j = 0; j < 16; j++) {
                if ((kMaskFn(i) >> j) & 1u) {
                    const int slot = (j == i - 1) ? 0 : (j == i) ? 1
                                   : (j == i + 1) ? 2 : 3;
                    float a = sm->ash[wid][i][slot][myh];   // broadcast LDS
                    ull ad = pack2(a, a);
                    ffma2(o0, ad, acc[j][0]);
                    ffma2(o1, ad, acc[j][1]);
                }
            }
            ull2 vv; vv.a = o0; vv.b = o1;
            *reinterpret_cast<ull2*>(&ob[i * 128 + 4 * lane]) = vv;
        }
    }
}

extern "C" void kernel_launch(void* const* d_in, const int* in_sizes, int n_in,
                              void* d_out, int out_size)
{
    const float* x  = (const float*)d_in[0];
    const float* W  = (const float*)d_in[1];
    const float* c2 = (const float*)d_in[2];   // att_vec OR adj (both 256 elems)
    const float* c3 = (const float*)d_in[3];   // the other one
    float* out = (float*)d_out;

    int n_batch = in_sizes[0] / 1024;   // 32768

    select_av_kernel<<<1, 256>>>(c2, c3);

    cudaFuncSetAttribute(gat_kernel, cudaFuncAttributeMaxDynamicSharedMemorySize,
                         (int)sizeof(SmemLayout));
    const int grid = 1024;              // 8192 warps -> 4 batches per warp
    gat_kernel<<<grid, THREADS, sizeof(SmemLayout)>>>(x, W, out,
                                                      n_batch, grid * WARPS);
}

// round 8
// speedup vs baseline: 1.1600x; 1.1600x over previous
#include <cuda_runtime.h>
#include <cstdint>

// GraphAttention: B=32768, N=16, FIN=64, H=4, FO=32 (C = H*FO = 128)
// One warp per batch, 192-thread CTAs, 3 CTAs/SM (18 warps, 112 regs).
// fp32 packed f32x2 FMA GEMM nf = x @ W, x stored UNduplicated in smem
// (broadcast LDS.128 + mov-pair packing). Scores fold to s = x @ wfold
// (reference einsum sums nf over heads). 4-neighbor softmax {i-1,i,i+1,i^8}.

typedef unsigned long long ull;
struct alignas(16) ull2 { ull a, b; };

static __device__ __forceinline__ void ffma2(ull& d, ull a, ull b) {
    asm("fma.rn.f32x2 %0, %1, %2, %0;" : "+l"(d) : "l"(a), "l"(b));
}
static __device__ __forceinline__ ull pack2(float lo, float hi) {
    ull r; asm("mov.b64 %0, {%1, %2};" : "=l"(r) : "f"(lo), "f"(hi)); return r;
}

constexpr int WARPS   = 6;
constexpr int THREADS = WARPS * 32;     // 192
constexpr int XST     = 68;             // float stride of x rows (272B = 17*16B)

__host__ __device__ constexpr unsigned kMaskFn(int i) {
    unsigned m = (1u << i) | (1u << (i ^ 8));
    if (i > 0)  m |= 1u << (i - 1);
    if (i < 15) m |= 1u << (i + 1);
    return m;
}

__device__ float g_av[256];   // selected att_vec

__global__ void select_av_kernel(const float* __restrict__ cand_a,
                                 const float* __restrict__ cand_b)
{
    __shared__ int a_nonbin;
    int t = threadIdx.x;             // 256 threads
    if (t == 0) a_nonbin = 0;
    __syncthreads();
    float va = cand_a[t];
    if (!(va == 0.0f || va == 1.0f)) atomicAdd(&a_nonbin, 1);
    __syncthreads();
    const float* src = (a_nonbin > 0) ? cand_a : cand_b;
    g_av[t] = src[t];
}

struct SmemLayout {
    float Ws[64][128];              // W row-major                    32 KB
    float wfold[64][2][4];          // folded score weights            2 KB
    float xs[WARPS][16 * XST];      // raw x rows (stride 68)       25.5 KB
    float sbuf[WARPS][2][16][4];    // s1/s2 per node per head         3 KB
    float ash[WARPS][16][4][4];     // attn[i][slot][h]                6 KB
};                                  // ~68.5 KB -> 3 CTAs/SM

__global__ void __launch_bounds__(THREADS, 3)
gat_kernel(const float* __restrict__ x, const float* __restrict__ W,
           float* __restrict__ out, int n_batch, int total_warps)
{
    extern __shared__ char sraw[];
    SmemLayout* sm = reinterpret_cast<SmemLayout*>(sraw);
    const int tid  = threadIdx.x;
    const int lane = tid & 31;
    const int wid  = tid >> 5;

    // ---- CTA init: copy W; build wfold from W and g_av.
    {
        const float4* Wg = reinterpret_cast<const float4*>(W);
        float4* Wd = reinterpret_cast<float4*>(&sm->Ws[0][0]);
        for (int idx = tid; idx < 64 * 32; idx += THREADS) Wd[idx] = Wg[idx];
        for (int e = tid; e < 512; e += THREADS) {
            int f = e >> 3, side = (e >> 2) & 1, h = e & 3;
            const float* wr = W + f * 128;
            const float* ar = g_av + h * 64 + side * 32;
            float s = 0.f;
            #pragma unroll 8
            for (int f2 = 0; f2 < 32; f2++) {
                float wsum = wr[f2] + wr[32 + f2] + wr[64 + f2] + wr[96 + f2];
                s += wsum * ar[f2];
            }
            sm->wfold[f][side][h] = s;
        }
    }
    __syncthreads();

    float* xs = sm->xs[wid];
    const int gw  = blockIdx.x * WARPS + wid;
    const int myh = lane >> 3;   // head owned by this lane's 4 columns

    for (int b = gw; b < n_batch; b += total_warps) {
        // ---- load x_b (1024 floats) straight into smem rows (no duplication)
        const float4* xg = reinterpret_cast<const float4*>(x + (size_t)b * 1024);
        __syncwarp();   // prior iter's xs reads complete before overwrite
        #pragma unroll
        for (int t = 0; t < 8; t++) {
            int g4 = t * 32 + lane;
            float4 v = xg[g4];
            int i = g4 >> 4, f0 = (g4 & 15) * 4;
            *reinterpret_cast<float4*>(&xs[i * XST + f0]) = v;
        }
        __syncwarp();

        // ---- GEMM: acc[i][0] = nf cols {4l,4l+1}, acc[i][1] = {4l+2,4l+3}
        ull acc[16][2];
        #pragma unroll
        for (int i = 0; i < 16; i++) { acc[i][0] = 0ull; acc[i][1] = 0ull; }

        #pragma unroll 2
        for (int fb = 0; fb < 64; fb += 4) {
            ull2 w0 = *reinterpret_cast<const ull2*>(&sm->Ws[fb    ][4 * lane]);
            ull2 w1 = *reinterpret_cast<const ull2*>(&sm->Ws[fb + 1][4 * lane]);
            ull2 w2 = *reinterpret_cast<const ull2*>(&sm->Ws[fb + 2][4 * lane]);
            ull2 w3 = *reinterpret_cast<const ull2*>(&sm->Ws[fb + 3][4 * lane]);
            #pragma unroll
            for (int i = 0; i < 16; i++) {
                float4 q = *reinterpret_cast<const float4*>(&xs[i * XST + fb]);
                ull xq0 = pack2(q.x, q.x);
                ull xq1 = pack2(q.y, q.y);
                ull xq2 = pack2(q.z, q.z);
                ull xq3 = pack2(q.w, q.w);
                ffma2(acc[i][0], xq0, w0.a); ffma2(acc[i][1], xq0, w0.b);
                ffma2(acc[i][0], xq1, w1.a); ffma2(acc[i][1], xq1, w1.b);
                ffma2(acc[i][0], xq2, w2.a); ffma2(acc[i][1], xq2, w2.b);
                ffma2(acc[i][0], xq3, w3.a); ffma2(acc[i][1], xq3, w3.b);
            }
        }

        // ---- s-phase (last reader of xs): s[side][si][h] = x[si,:].wfold[:,side,h]
        {
            int si = lane & 15, side = lane >> 4;
            const float* xrow = &xs[si * XST];
            float s0 = 0.f, s1 = 0.f, s2 = 0.f, s3 = 0.f;
            #pragma unroll 4
            for (int k = 0; k < 16; k++) {
                float4 q  = *reinterpret_cast<const float4*>(&xrow[4 * k]);
                float4 wA = *reinterpret_cast<const float4*>(&sm->wfold[4 * k    ][side][0]);
                float4 wB = *reinterpret_cast<const float4*>(&sm->wfold[4 * k + 1][side][0]);
                float4 wC = *reinterpret_cast<const float4*>(&sm->wfold[4 * k + 2][side][0]);
                float4 wD = *reinterpret_cast<const float4*>(&sm->wfold[4 * k + 3][side][0]);
                s0 += q.x * wA.x + q.y * wB.x + q.z * wC.x + q.w * wD.x;
                s1 += q.x * wA.y + q.y * wB.y + q.z * wC.y + q.w * wD.y;
                s2 += q.x * wA.z + q.y * wB.z + q.z * wC.z + q.w * wD.z;
                s3 += q.x * wA.w + q.y * wB.w + q.z * wC.w + q.w * wD.w;
            }
            *reinterpret_cast<float4*>(&sm->sbuf[wid][side][si][0]) =
                make_float4(s0, s1, s2, s3);
        }
        __syncwarp();

        // ---- softmax over {i-1, i, i+1, i^8}: lane -> (node i, head pair hp)
        {
            int i = lane & 15, hp = lane >> 4;
            float2 s1v = *reinterpret_cast<const float2*>(&sm->sbuf[wid][0][i][2 * hp]);
            int  jn[4] = { (i > 0) ? i - 1 : i, i, (i < 15) ? i + 1 : i, i ^ 8 };
            bool vl[4] = { i > 0, true, i < 15, true };
            float t0[4], t1[4];
            float m0 = -1e30f, m1 = -1e30f;
            #pragma unroll
            for (int s = 0; s < 4; s++) {
                float2 s2v = *reinterpret_cast<const float2*>(&sm->sbuf[wid][1][jn[s]][2 * hp]);
                float a0 = s1v.x + s2v.x; a0 = fmaxf(a0, 0.2f * a0);
                float a1 = s1v.y + s2v.y; a1 = fmaxf(a1, 0.2f * a1);
                t0[s] = vl[s] ? a0 : -1e30f;
                t1[s] = vl[s] ? a1 : -1e30f;
                m0 = fmaxf(m0, t0[s]); m1 = fmaxf(m1, t1[s]);
            }
            float sum0 = 0.f, sum1 = 0.f;
            #pragma unroll
            for (int s = 0; s < 4; s++) {
                t0[s] = __expf(t0[s] - m0);   // invalid -> 0
                t1[s] = __expf(t1[s] - m1);
                sum0 += t0[s]; sum1 += t1[s];
            }
            float r0 = __fdividef(1.f, sum0), r1 = __fdividef(1.f, sum1);
            #pragma unroll
            for (int s = 0; s < 4; s++)
                *reinterpret_cast<float2*>(&sm->ash[wid][i][s][2 * hp]) =
                    make_float2(t0[s] * r0, t1[s] * r1);
        }
        __syncwarp();

        // ---- agg over compile-time masked (i,j) + STG.128 store
        float* ob = out + (size_t)b * 2048;
        #pragma unroll
        for (int i = 0; i < 16; i++) {
            ull o0 = 0ull, o1 = 0ull;
            #pragma unroll
            for (int j = 0; j < 16; j++) {
                if ((kMaskFn(i) >> j) & 1u) {
                    const int slot = (j == i - 1) ? 0 : (j == i) ? 1
                                   : (j == i + 1) ? 2 : 3;
                    float a = sm->ash[wid][i][slot][myh];   // broadcast LDS
                    ull ad = pack2(a, a);
                    ffma2(o0, ad, acc[j][0]);
                    ffma2(o1, ad, acc[j][1]);
                }
            }
            ull2 vv; vv.a = o0; vv.b = o1;
            *reinterpret_cast<ull2*>(&ob[i * 128 + 4 * lane]) = vv;
        }
    }
}

extern "C" void kernel_launch(void* const* d_in, const int* in_sizes, int n_in,
                              void* d_out, int out_size)
{
    const float* x  = (const float*)d_in[0];
    const float* W  = (const float*)d_in[1];
    const float* c2 = (const float*)d_in[2];   // att_vec OR adj (both 256 elems)
    const float* c3 = (const float*)d_in[3];   // the other one
    float* out = (float*)d_out;

    int n_batch = in_sizes[0] / 1024;   // 32768

    select_av_kernel<<<1, 256>>>(c2, c3);

    cudaFuncSetAttribute(gat_kernel, cudaFuncAttributeMaxDynamicSharedMemorySize,
                         (int)sizeof(SmemLayout));
    const int grid = 444;               // 148 SM x 3 CTAs, single wave
    gat_kernel<<<grid, THREADS, sizeof(SmemLayout)>>>(x, W, out,
                                                      n_batch, grid * WARPS);
}

// round 9
// speedup vs baseline: 1.1656x; 1.0048x over previous
#include <cuda_runtime.h>
#include <cstdint>

// GraphAttention: B=32768, N=16, FIN=64, H=4, FO=32 (C = H*FO = 128)
// One warp per batch, 192-thread CTAs, 3 CTAs/SM (18 warps, 112 regs).
// fp32 packed f32x2 FMA GEMM nf = x @ W, x stored UNduplicated in smem
// (broadcast LDS.128 + mov-pair packing). Scores fold to s = x @ wfold
// (reference einsum sums nf over heads). 4-neighbor softmax {i-1,i,i+1,i^8}.

typedef unsigned long long ull;
struct alignas(16) ull2 { ull a, b; };

static __device__ __forceinline__ void ffma2(ull& d, ull a, ull b) {
    asm("fma.rn.f32x2 %0, %1, %2, %0;" : "+l"(d) : "l"(a), "l"(b));
}
static __device__ __forceinline__ ull pack2(float lo, float hi) {
    ull r; asm("mov.b64 %0, {%1, %2};" : "=l"(r) : "f"(lo), "f"(hi)); return r;
}

constexpr int WARPS   = 6;
constexpr int THREADS = WARPS * 32;     // 192
constexpr int XST     = 68;             // float stride of x rows (272B = 17*16B)

__host__ __device__ constexpr unsigned kMaskFn(int i) {
    unsigned m = (1u << i) | (1u << (i ^ 8));
    if (i > 0)  m |= 1u << (i - 1);
    if (i < 15) m |= 1u << (i + 1);
    return m;
}

__device__ float g_av[256];   // selected att_vec

__global__ void select_av_kernel(const float* __restrict__ cand_a,
                                 const float* __restrict__ cand_b)
{
    __shared__ int a_nonbin;
    int t = threadIdx.x;             // 256 threads
    if (t == 0) a_nonbin = 0;
    __syncthreads();
    float va = cand_a[t];
    if (!(va == 0.0f || va == 1.0f)) atomicAdd(&a_nonbin, 1);
    __syncthreads();
    const float* src = (a_nonbin > 0) ? cand_a : cand_b;
    g_av[t] = src[t];
}

struct SmemLayout {
    float Ws[64][128];              // W row-major                    32 KB
    float wfold[64][2][4];          // folded score weights            2 KB
    float xs[WARPS][16 * XST];      // raw x rows (stride 68)       25.5 KB
    float sbuf[WARPS][2][16][4];    // s1/s2 per node per head         3 KB
    float ash[WARPS][16][4][4];     // attn[i][slot][h]                6 KB
};                                  // ~68.5 KB -> 3 CTAs/SM

__global__ void __launch_bounds__(THREADS, 3)
gat_kernel(const float* __restrict__ x, const float* __restrict__ W,
           float* __restrict__ out, int n_batch, int total_warps)
{
    extern __shared__ char sraw[];
    SmemLayout* sm = reinterpret_cast<SmemLayout*>(sraw);
    const int tid  = threadIdx.x;
    const int lane = tid & 31;
    const int wid  = tid >> 5;

    // ---- CTA init: copy W; build wfold from W and g_av.
    {
        const float4* Wg = reinterpret_cast<const float4*>(W);
        float4* Wd = reinterpret_cast<float4*>(&sm->Ws[0][0]);
        for (int idx = tid; idx < 64 * 32; idx += THREADS) Wd[idx] = Wg[idx];
        for (int e = tid; e < 512; e += THREADS) {
            int f = e >> 3, side = (e >> 2) & 1, h = e & 3;
            const float* wr = W + f * 128;
            const float* ar = g_av + h * 64 + side * 32;
            float s = 0.f;
            #pragma unroll 8
            for (int f2 = 0; f2 < 32; f2++) {
                float wsum = wr[f2] + wr[32 + f2] + wr[64 + f2] + wr[96 + f2];
                s += wsum * ar[f2];
            }
            sm->wfold[f][side][h] = s;
        }
    }
    __syncthreads();

    float* xs = sm->xs[wid];
    const int gw  = blockIdx.x * WARPS + wid;
    const int myh = lane >> 3;   // head owned by this lane's 4 columns

    for (int b = gw; b < n_batch; b += total_warps) {
        // ---- load x_b (1024 floats) straight into smem rows (no duplication)
        const float4* xg = reinterpret_cast<const float4*>(x + (size_t)b * 1024);
        __syncwarp();   // prior iter's xs reads complete before overwrite
        #pragma unroll
        for (int t = 0; t < 8; t++) {
            int g4 = t * 32 + lane;
            float4 v = xg[g4];
            int i = g4 >> 4, f0 = (g4 & 15) * 4;
            *reinterpret_cast<float4*>(&xs[i * XST + f0]) = v;
        }
        __syncwarp();

        // ---- GEMM: acc[i][0] = nf cols {4l,4l+1}, acc[i][1] = {4l+2,4l+3}
        ull acc[16][2];
        #pragma unroll
        for (int i = 0; i < 16; i++) { acc[i][0] = 0ull; acc[i][1] = 0ull; }

        #pragma unroll 2
        for (int fb = 0; fb < 64; fb += 4) {
            ull2 w0 = *reinterpret_cast<const ull2*>(&sm->Ws[fb    ][4 * lane]);
            ull2 w1 = *reinterpret_cast<const ull2*>(&sm->Ws[fb + 1][4 * lane]);
            ull2 w2 = *reinterpret_cast<const ull2*>(&sm->Ws[fb + 2][4 * lane]);
            ull2 w3 = *reinterpret_cast<const ull2*>(&sm->Ws[fb + 3][4 * lane]);
            #pragma unroll
            for (int i = 0; i < 16; i++) {
                float4 q = *reinterpret_cast<const float4*>(&xs[i * XST + fb]);
                ull xq0 = pack2(q.x, q.x);
                ull xq1 = pack2(q.y, q.y);
                ull xq2 = pack2(q.z, q.z);
                ull xq3 = pack2(q.w, q.w);
                ffma2(acc[i][0], xq0, w0.a); ffma2(acc[i][1], xq0, w0.b);
                ffma2(acc[i][0], xq1, w1.a); ffma2(acc[i][1], xq1, w1.b);
                ffma2(acc[i][0], xq2, w2.a); ffma2(acc[i][1], xq2, w2.b);
                ffma2(acc[i][0], xq3, w3.a); ffma2(acc[i][1], xq3, w3.b);
            }
        }

        // ---- s-phase (last reader of xs): s[side][si][h] = x[si,:].wfold[:,side,h]
        {
            int si = lane & 15, side = lane >> 4;
            const float* xrow = &xs[si * XST];
            float s0 = 0.f, s1 = 0.f, s2 = 0.f, s3 = 0.f;
            #pragma unroll 4
            for (int k = 0; k < 16; k++) {
                float4 q  = *reinterpret_cast<const float4*>(&xrow[4 * k]);
                float4 wA = *reinterpret_cast<const float4*>(&sm->wfold[4 * k    ][side][0]);
                float4 wB = *reinterpret_cast<const float4*>(&sm->wfold[4 * k + 1][side][0]);
                float4 wC = *reinterpret_cast<const float4*>(&sm->wfold[4 * k + 2][side][0]);
                float4 wD = *reinterpret_cast<const float4*>(&sm->wfold[4 * k + 3][side][0]);
                s0 += q.x * wA.x + q.y * wB.x + q.z * wC.x + q.w * wD.x;
                s1 += q.x * wA.y + q.y * wB.y + q.z * wC.y + q.w * wD.y;
                s2 += q.x * wA.z + q.y * wB.z + q.z * wC.z + q.w * wD.z;
                s3 += q.x * wA.w + q.y * wB.w + q.z * wC.w + q.w * wD.w;
            }
            *reinterpret_cast<float4*>(&sm->sbuf[wid][side][si][0]) =
                make_float4(s0, s1, s2, s3);
        }
        __syncwarp();

        // ---- softmax over {i-1, i, i+1, i^8}: lane -> (node i, head pair hp)
        {
            int i = lane & 15, hp = lane >> 4;
            float2 s1v = *reinterpret_cast<const float2*>(&sm->sbuf[wid][0][i][2 * hp]);
            int  jn[4] = { (i > 0) ? i - 1 : i, i, (i < 15) ? i + 1 : i, i ^ 8 };
            bool vl[4] = { i > 0, true, i < 15, true };
            float t0[4], t1[4];
            float m0 = -1e30f, m1 = -1e30f;
            #pragma unroll
            for (int s = 0; s < 4; s++) {
                float2 s2v = *reinterpret_cast<const float2*>(&sm->sbuf[wid][1][jn[s]][2 * hp]);
                float a0 = s1v.x + s2v.x; a0 = fmaxf(a0, 0.2f * a0);
                float a1 = s1v.y + s2v.y; a1 = fmaxf(a1, 0.2f * a1);
                t0[s] = vl[s] ? a0 : -1e30f;
                t1[s] = vl[s] ? a1 : -1e30f;
                m0 = fmaxf(m0, t0[s]); m1 = fmaxf(m1, t1[s]);
            }
            float sum0 = 0.f, sum1 = 0.f;
            #pragma unroll
            for (int s = 0; s < 4; s++) {
                t0[s] = __expf(t0[s] - m0);   // invalid -> 0
                t1[s] = __expf(t1[s] - m1);
                sum0 += t0[s]; sum1 += t1[s];
            }
            float r0 = __fdividef(1.f, sum0), r1 = __fdividef(1.f, sum1);
            #pragma unroll
            for (int s = 0; s < 4; s++)
                *reinterpret_cast<float2*>(&sm->ash[wid][i][s][2 * hp]) =
                    make_float2(t0[s] * r0, t1[s] * r1);
        }
        __syncwarp();

        // ---- agg over compile-time masked (i,j) + STG.128 store
        float* ob = out + (size_t)b * 2048;
        #pragma unroll
        for (int i = 0; i < 16; i++) {
            ull o0 = 0ull, o1 = 0ull;
            #pragma unroll
            for (int j = 0; j < 16; j++) {
                if ((kMaskFn(i) >> j) & 1u) {
                    const int slot = (j == i - 1) ? 0 : (j == i) ? 1
                                   : (j == i + 1) ? 2 : 3;
                    float a = sm->ash[wid][i][slot][myh];   // broadcast LDS
                    ull ad = pack2(a, a);
                    ffma2(o0, ad, acc[j][0]);
                    ffma2(o1, ad, acc[j][1]);
                }
            }
            ull2 vv; vv.a = o0; vv.b = o1;
            *reinterpret_cast<ull2*>(&ob[i * 128 + 4 * lane]) = vv;
        }
    }
}

extern "C" void kernel_launch(void* const* d_in, const int* in_sizes, int n_in,
                              void* d_out, int out_size)
{
    const float* x  = (const float*)d_in[0];
    const float* W  = (const float*)d_in[1];
    const float* c2 = (const float*)d_in[2];   // att_vec OR adj (both 256 elems)
    const float* c3 = (const float*)d_in[3];   // the other one
    float* out = (float*)d_out;

    int n_batch = in_sizes[0] / 1024;   // 32768

    select_av_kernel<<<1, 256>>>(c2, c3);

    cudaFuncSetAttribute(gat_kernel, cudaFuncAttributeMaxDynamicSharedMemorySize,
                         (int)sizeof(SmemLayout));
    const int grid = 444;               // 148 SM x 3 CTAs, single wave
    gat_kernel<<<grid, THREADS, sizeof(SmemLayout)>>>(x, W, out,
                                                      n_batch, grid * WARPS);
}

// round 12
// speedup vs baseline: 2.0134x; 1.7274x over previous
#include <cuda_runtime.h>
#include <cuda_bf16.h>
#include <cstdint>

// GAT B=32768, N=16, FIN=64, H=4, FO=32. nf = X@W on tensor cores via
// mma.sync.m16n8k16 bf16 3-split (no sm_103a-only PTX). Scores = X@wfoldT
// via the same A fragments. Softmax/agg on CUDA cores (validated R8 logic).
typedef unsigned long long ull;
struct alignas(16) ull2x { ull a, b; };

#define WTHI 0
#define WTLO 18432
#define WFHI 36864
#define WFLO 38016
#define PWB  39168
#define A_HI 0
#define A_LO 2304
#define NF_  4608
#define SB_  13056
#define ASH_ 13568
#define PWSZ 15616
#define SMEM_SZ (PWB + 4 * PWSZ)     // 101632 B -> 2 CTAs/SM

static __device__ __forceinline__ uint32_t s2u(const void* p) {
    uint32_t a;
    asm("{ .reg .u64 t; cvta.to.shared.u64 t, %1; cvt.u32.u64 %0, t; }" : "=r"(a) : "l"(p));
    return a;
}
static __device__ __forceinline__ void ffma2(ull& d, ull a, ull b) {
    asm("fma.rn.f32x2 %0, %1, %2, %0;" : "+l"(d) : "l"(a), "l"(b));
}
static __device__ __forceinline__ uint32_t cvt2(float lo, float hi) {
    uint32_t r; asm("cvt.rn.satfinite.bf16x2.f32 %0, %1, %2;" : "=r"(r) : "f"(hi), "f"(lo));
    return r;   // {hi:bf16(hi), lo:bf16(lo)} -> memory order [lo, hi]
}
static __device__ __forceinline__ void ldmx4(uint32_t& r0, uint32_t& r1, uint32_t& r2,
                                             uint32_t& r3, uint32_t addr) {
    asm volatile("ldmatrix.sync.aligned.m8n8.x4.shared.b16 {%0,%1,%2,%3}, [%4];"
                 : "=r"(r0), "=r"(r1), "=r"(r2), "=r"(r3) : "r"(addr));
}
static __device__ __forceinline__ void mma4(float* d, const uint32_t* a,
                                            uint32_t b0, uint32_t b1) {
    asm volatile("mma.sync.aligned.m16n8k16.row.col.f32.bf16.bf16.f32 "
                 "{%0,%1,%2,%3},{%4,%5,%6,%7},{%8,%9},{%0,%1,%2,%3};"
                 : "+f"(d[0]), "+f"(d[1]), "+f"(d[2]), "+f"(d[3])
                 : "r"(a[0]), "r"(a[1]), "r"(a[2]), "r"(a[3]), "r"(b0), "r"(b1));
}

__device__ float g_av[256];
__global__ void select_av_kernel(const float* __restrict__ ca, const float* __restrict__ cb) {
    __shared__ int nb; int t = threadIdx.x;
    if (t == 0) nb = 0;
    __syncthreads();
    float v = ca[t];
    if (!(v == 0.0f || v == 1.0f)) atomicAdd(&nb, 1);
    __syncthreads();
    g_av[t] = (nb > 0) ? ca[t] : cb[t];
}

__global__ void __launch_bounds__(128)
gat_kernel(const float* __restrict__ x, const float* __restrict__ W,
           float* __restrict__ out, int n_batch)
{
    extern __shared__ char sm[];
    const uint32_t sb = s2u(sm);
    const int tid = threadIdx.x, lane = tid & 31, wid = tid >> 5;

    // ---- init: Wt hi/lo (K-major rows, 144B pitch) + wfoldT hi/lo ----
    for (int idx = tid; idx < 8192; idx += 128) {
        int cg = idx >> 6, f = idx & 63;
        float w = W[f * 128 + cg];
        __nv_bfloat16 h = __float2bfloat16_rn(w);
        *reinterpret_cast<__nv_bfloat16*>(sm + WTHI + cg * 144 + f * 2) = h;
        *reinterpret_cast<__nv_bfloat16*>(sm + WTLO + cg * 144 + f * 2) =
            __float2bfloat16_rn(w - __bfloat162float(h));
    }
    for (int e = tid; e < 512; e += 128) {
        int f = e >> 3, n = e & 7, side = n >> 2, h = n & 3;
        const float* wr = W + f * 128;
        const float* ar = g_av + h * 64 + side * 32;
        float s = 0.f;
        #pragma unroll 8
        for (int k = 0; k < 32; k++)
            s += (wr[k] + wr[32 + k] + wr[64 + k] + wr[96 + k]) * ar[k];
        __nv_bfloat16 hb = __float2bfloat16_rn(s);
        *reinterpret_cast<__nv_bfloat16*>(sm + WFHI + n * 144 + f * 2) = hb;
        *reinterpret_cast<__nv_bfloat16*>(sm + WFLO + n * 144 + f * 2) =
            __float2bfloat16_rn(s - __bfloat162float(hb));
    }
    __syncthreads();

    char* pw = sm + PWB + wid * PWSZ;
    const uint32_t aw = sb + PWB + wid * PWSZ;
    const int myh = lane >> 3;

    for (int b = blockIdx.x * 4 + wid; b < n_batch; b += gridDim.x * 4) {
        // ---- X -> bf16 hi/lo A tiles (row pitch 144B) ----
        const float4* xg = reinterpret_cast<const float4*>(x + (size_t)b * 1024);
        #pragma unroll
        for (int t = 0; t < 8; t++) {
            int fid = t * 32 + lane;
            float4 v = xg[fid];
            uint32_t h01 = cvt2(v.x, v.y), h23 = cvt2(v.z, v.w);
            float l0 = v.x - __uint_as_float(h01 << 16);
            float l1 = v.y - __uint_as_float(h01 & 0xFFFF0000u);
            float l2 = v.z - __uint_as_float(h23 << 16);
            float l3 = v.w - __uint_as_float(h23 & 0xFFFF0000u);
            int off = (fid >> 4) * 144 + (fid & 15) * 8;
            *reinterpret_cast<uint2*>(pw + A_HI + off) = make_uint2(h01, h23);
            *reinterpret_cast<uint2*>(pw + A_LO + off) = make_uint2(cvt2(l0, l1), cvt2(l2, l3));
        }
        __syncwarp();

        // ---- A fragments (4 k-steps, hi and lo) ----
        uint32_t ah[16], al[16];
        {
            uint32_t ab = aw + A_HI + (lane & 15) * 144 + (lane >> 4) * 16;
            #pragma unroll
            for (int kt = 0; kt < 4; kt++)
                ldmx4(ah[4 * kt], ah[4 * kt + 1], ah[4 * kt + 2], ah[4 * kt + 3], ab + kt * 32);
            uint32_t lb = ab + (A_LO - A_HI);
            #pragma unroll
            for (int kt = 0; kt < 4; kt++)
                ldmx4(al[4 * kt], al[4 * kt + 1], al[4 * kt + 2], al[4 * kt + 3], lb + kt * 32);
        }

        // ---- scores via mma: s(16x8) = X @ wfoldT^T ----
        {
            uint32_t fb = sb + WFHI + (lane & 7) * 144 + (lane >> 3) * 16;
            uint32_t fh[8], fl[8];
            ldmx4(fh[0], fh[1], fh[2], fh[3], fb);
            ldmx4(fh[4], fh[5], fh[6], fh[7], fb + 64);
            ldmx4(fl[0], fl[1], fl[2], fl[3], fb + (WFLO - WFHI));
            ldmx4(fl[4], fl[5], fl[6], fl[7], fb + (WFLO - WFHI) + 64);
            float s[4] = {0.f, 0.f, 0.f, 0.f};
            #pragma unroll
            for (int kt = 0; kt < 4; kt++) {
                int bi = (kt >> 1) * 4 + (kt & 1) * 2;
                mma4(s, &ah[4 * kt], fh[bi], fh[bi + 1]);
            }
            #pragma unroll
            for (int kt = 0; kt < 4; kt++) {
                int bi = (kt >> 1) * 4 + (kt & 1) * 2;
                mma4(s, &al[4 * kt], fh[bi], fh[bi + 1]);
            }
            #pragma unroll
            for (int kt = 0; kt < 4; kt++) {
                int bi = (kt >> 1) * 4 + (kt & 1) * 2;
                mma4(s, &ah[4 * kt], fl[bi], fl[bi + 1]);
            }
            int c = 2 * (lane & 3), r = lane >> 2, side = c >> 2, cc = c & 3;
            *reinterpret_cast<float2*>(pw + SB_ + (side * 16 + r) * 16 + cc * 4) =
                make_float2(s[0], s[1]);
            *reinterpret_cast<float2*>(pw + SB_ + (side * 16 + r + 8) * 16 + cc * 4) =
                make_float2(s[2], s[3]);
        }
        __syncwarp();

        // ---- softmax over {i-1,i,i+1,i^8}; ash[i][h][slot] = {a,a} ----
        {
            int i = lane & 15, hp = lane >> 4;
            float2 s1v = *reinterpret_cast<const float2*>(pw + SB_ + i * 16 + hp * 8);
            int jn[4] = { (i > 0) ? i - 1 : i, i, (i < 15) ? i + 1 : i, i ^ 8 };
            bool vl[4] = { i > 0, true, i < 15, true };
            float t0[4], t1[4];
            float m0 = -1e30f, m1 = -1e30f;
            #pragma unroll
            for (int s = 0; s < 4; s++) {
                float2 s2v = *reinterpret_cast<const float2*>(pw + SB_ + 256 + jn[s] * 16 + hp * 8);
                float a0 = s1v.x + s2v.x; a0 = fmaxf(a0, 0.2f * a0);
                float a1 = s1v.y + s2v.y; a1 = fmaxf(a1, 0.2f * a1);
                t0[s] = vl[s] ? a0 : -1e30f;
                t1[s] = vl[s] ? a1 : -1e30f;
                m0 = fmaxf(m0, t0[s]); m1 = fmaxf(m1, t1[s]);
            }
            float sum0 = 0.f, sum1 = 0.f;
            #pragma unroll
            for (int s = 0; s < 4; s++) {
                t0[s] = __expf(t0[s] - m0);
                t1[s] = __expf(t1[s] - m1);
                sum0 += t0[s]; sum1 += t1[s];
            }
            float r0 = __fdividef(1.f, sum0), r1 = __fdividef(1.f, sum1);
            #pragma unroll
            for (int s = 0; s < 4; s++) {
                float v0 = t0[s] * r0, v1 = t1[s] * r1;
                *reinterpret_cast<float2*>(pw + ASH_ + ((i * 4 + 2 * hp) * 4 + s) * 8) =
                    make_float2(v0, v0);
                *reinterpret_cast<float2*>(pw + ASH_ + ((i * 4 + 2 * hp + 1) * 4 + s) * 8) =
                    make_float2(v1, v1);
            }
        }

        // ---- main GEMM: nf = X@W, 16 n-tiles, 3-split, stage D to nf smem ----
        for (int nt = 0; nt < 16; nt += 2) {
            uint32_t wb0 = sb + WTHI + (nt * 8 + (lane & 7)) * 144 + (lane >> 3) * 16;
            uint32_t wb1 = wb0 + 8 * 144;
            uint32_t bh0[8], bl0[8], bh1[8], bl1[8];
            ldmx4(bh0[0], bh0[1], bh0[2], bh0[3], wb0);
            ldmx4(bh0[4], bh0[5], bh0[6], bh0[7], wb0 + 64);
            ldmx4(bh1[0], bh1[1], bh1[2], bh1[3], wb1);
            ldmx4(bh1[4], bh1[5], bh1[6], bh1[7], wb1 + 64);
            ldmx4(bl0[0], bl0[1], bl0[2], bl0[3], wb0 + (WTLO - WTHI));
            ldmx4(bl0[4], bl0[5], bl0[6], bl0[7], wb0 + (WTLO - WTHI) + 64);
            ldmx4(bl1[0], bl1[1], bl1[2], bl1[3], wb1 + (WTLO - WTHI));
            ldmx4(bl1[4], bl1[5], bl1[6], bl1[7], wb1 + (WTLO - WTHI) + 64);

            float d0[4] = {0.f, 0.f, 0.f, 0.f}, d1[4] = {0.f, 0.f, 0.f, 0.f};
            #pragma unroll
            for (int kt = 0; kt < 4; kt++) {
                int bi = (kt >> 1) * 4 + (kt & 1) * 2;
                mma4(d0, &ah[4 * kt], bh0[bi], bh0[bi + 1]);
                mma4(d1, &ah[4 * kt], bh1[bi], bh1[bi + 1]);
            }
            #pragma unroll
            for (int kt = 0; kt < 4; kt++) {
                int bi = (kt >> 1) * 4 + (kt & 1) * 2;
                mma4(d0, &al[4 * kt], bh0[bi], bh0[bi + 1]);
                mma4(d1, &al[4 * kt], bh1[bi], bh1[bi + 1]);
            }
            #pragma unroll
            for (int kt = 0; kt < 4; kt++) {
                int bi = (kt >> 1) * 4 + (kt & 1) * 2;
                mma4(d0, &ah[4 * kt], bl0[bi], bl0[bi + 1]);
                mma4(d1, &ah[4 * kt], bl1[bi], bl1[bi + 1]);
            }
            int c = 2 * (lane & 3), r = lane >> 2;
            *reinterpret_cast<float2*>(pw + NF_ + r * 528 + (nt * 8 + c) * 4) =
                make_float2(d0[0], d0[1]);
            *reinterpret_cast<float2*>(pw + NF_ + (r + 8) * 528 + (nt * 8 + c) * 4) =
                make_float2(d0[2], d0[3]);
            *reinterpret_cast<float2*>(pw + NF_ + r * 528 + ((nt + 1) * 8 + c) * 4) =
                make_float2(d1[0], d1[1]);
            *reinterpret_cast<float2*>(pw + NF_ + (r + 8) * 528 + ((nt + 1) * 8 + c) * 4) =
                make_float2(d1[2], d1[3]);
        }
        __syncwarp();

        // ---- agg over {i-1,i,i+1,i^8} + STG.128 ----
        float* ob = out + (size_t)b * 2048;
        #pragma unroll
        for (int i = 0; i < 16; i++) {
            int jn0 = (i > 0) ? i - 1 : i, jn2 = (i < 15) ? i + 1 : i;
            ull a0 = *reinterpret_cast<const ull*>(pw + ASH_ + ((i * 4 + myh) * 4 + 0) * 8);
            ull a1 = *reinterpret_cast<const ull*>(pw + ASH_ + ((i * 4 + myh) * 4 + 1) * 8);
            ull a2 = *reinterpret_cast<const ull*>(pw + ASH_ + ((i * 4 + myh) * 4 + 2) * 8);
            ull a3 = *reinterpret_cast<const ull*>(pw + ASH_ + ((i * 4 + myh) * 4 + 3) * 8);
            ull2x q0 = *reinterpret_cast<const ull2x*>(pw + NF_ + jn0 * 528 + lane * 16);
            ull2x q1 = *reinterpret_cast<const ull2x*>(pw + NF_ + i   * 528 + lane * 16);
            ull2x q2 = *reinterpret_cast<const ull2x*>(pw + NF_ + jn2 * 528 + lane * 16);
            ull2x q3 = *reinterpret_cast<const ull2x*>(pw + NF_ + (i ^ 8) * 528 + lane * 16);
            ull o0 = 0ull, o1 = 0ull;
            ffma2(o0, a0, q0.a); ffma2(o1, a0, q0.b);
            ffma2(o0, a1, q1.a); ffma2(o1, a1, q1.b);
            ffma2(o0, a2, q2.a); ffma2(o1, a2, q2.b);
            ffma2(o0, a3, q3.a); ffma2(o1, a3, q3.b);
            ull2x vv; vv.a = o0; vv.b = o1;
            *reinterpret_cast<ull2x*>(&ob[i * 128 + 4 * lane]) = vv;
        }
        __syncwarp();
    }
}

extern "C" void kernel_launch(void* const* d_in, const int* in_sizes, int n_in,
                              void* d_out, int out_size)
{
    const float* x  = (const float*)d_in[0];
    const float* W  = (const float*)d_in[1];
    const float* c2 = (const float*)d_in[2];
    const float* c3 = (const float*)d_in[3];
    float* out = (float*)d_out;
    int n_batch = in_sizes[0] / 1024;   // 32768

    select_av_kernel<<<1, 256>>>(c2, c3);
    cudaFuncSetAttribute(gat_kernel, cudaFuncAttributeMaxDynamicSharedMemorySize, SMEM_SZ);
    gat_kernel<<<296, 128, SMEM_SZ>>>(x, W, out, n_batch);
}